// round 4
// baseline (speedup 1.0000x reference)
#include <cuda_runtime.h>

#define N_NODES 100000
#define N_EDGES 1600000
#define F 64
#define SCAN_B 512
#define N_SCANB ((N_NODES + SCAN_B - 1) / SCAN_B)   // 196

// ---- scratch (static __device__, no allocation) ----
__device__ int   g_is64;                  // 1 if edge_index is int64, 0 if int32
__device__ int   g_indeg[N_NODES];
__device__ int   g_start[N_NODES];
__device__ int   g_cur[N_NODES];
__device__ int   g_bsum[256];
__device__ int   g_boff[256];
__device__ float g_dinv[N_NODES];
__device__ int   g_csr[N_EDGES];          // src node per CSR slot (grouped by dst)
__device__ float g_hs[N_NODES * F];       // (x @ W) * dinv[row]
__device__ float g_z[N_NODES * F];        // relu(dinv*sum + b)  (activated features)

// ---------------------------------------------------------------------------
// Edge-index dtype probe: if the first 64 int64-interpreted slots are all
// valid node ids, the buffer is int64; otherwise it is int32 (JAX x64-off).
// ---------------------------------------------------------------------------
__global__ void k_detect(const long long* __restrict__ p64) {
    __shared__ int ok;
    if (threadIdx.x == 0) ok = 1;
    __syncthreads();
    long long v = p64[threadIdx.x];
    if (v < 0 || v >= N_NODES) ok = 0;   // racy all-write-0: benign
    __syncthreads();
    if (threadIdx.x == 0) g_is64 = ok;
}

__global__ void k_zero_indeg() {
    int i = blockIdx.x * blockDim.x + threadIdx.x;
    if (i < N_NODES) g_indeg[i] = 0;
}

__global__ void k_count(const void* __restrict__ ei) {
    int e = blockIdx.x * blockDim.x + threadIdx.x;
    if (e >= N_EDGES) return;
    int d = g_is64 ? (int)((const long long*)ei)[N_EDGES + e]
                   : ((const int*)ei)[N_EDGES + e];
    if ((unsigned)d < N_NODES) atomicAdd(&g_indeg[d], 1);
}

// exclusive scan of indeg, 3-phase
__global__ void __launch_bounds__(SCAN_B) k_scan1() {
    __shared__ int sh[SCAN_B];
    int i = blockIdx.x * SCAN_B + threadIdx.x;
    int v = (i < N_NODES) ? g_indeg[i] : 0;
    sh[threadIdx.x] = v;
    __syncthreads();
    for (int off = 1; off < SCAN_B; off <<= 1) {
        int t = (threadIdx.x >= off) ? sh[threadIdx.x - off] : 0;
        __syncthreads();
        sh[threadIdx.x] += t;
        __syncthreads();
    }
    if (i < N_NODES) g_start[i] = sh[threadIdx.x] - v;  // exclusive within block
    if (threadIdx.x == SCAN_B - 1) g_bsum[blockIdx.x] = sh[SCAN_B - 1];
}

__global__ void __launch_bounds__(256) k_scan2() {
    __shared__ int sh[256];
    int v = (threadIdx.x < N_SCANB) ? g_bsum[threadIdx.x] : 0;
    sh[threadIdx.x] = v;
    __syncthreads();
    for (int off = 1; off < 256; off <<= 1) {
        int t = (threadIdx.x >= off) ? sh[threadIdx.x - off] : 0;
        __syncthreads();
        sh[threadIdx.x] += t;
        __syncthreads();
    }
    g_boff[threadIdx.x] = sh[threadIdx.x] - v;  // exclusive
}

__global__ void k_scan3() {
    int i = blockIdx.x * blockDim.x + threadIdx.x;
    if (i < N_NODES) {
        int st = g_start[i] + g_boff[i / SCAN_B];
        g_start[i] = st;
        g_cur[i]   = st;
        g_dinv[i]  = rsqrtf((float)(g_indeg[i] + 1));  // +1 self loop
    }
}

__global__ void k_fill(const void* __restrict__ ei) {
    int e = blockIdx.x * blockDim.x + threadIdx.x;
    if (e >= N_EDGES) return;
    int s, d;
    if (g_is64) {
        s = (int)((const long long*)ei)[e];
        d = (int)((const long long*)ei)[N_EDGES + e];
    } else {
        s = ((const int*)ei)[e];
        d = ((const int*)ei)[N_EDGES + e];
    }
    if ((unsigned)s < N_NODES && (unsigned)d < N_NODES) {
        int slot = atomicAdd(&g_cur[d], 1);
        if ((unsigned)slot < N_EDGES) g_csr[slot] = s;
    }
}

// ---------------------------------------------------------------------------
// hs = (X @ W) * dinv[row].
//   L == 0: X = harness input pointer (raw h)
//   L == 1: X = g_z (device-side symbol reference only)
// Block (16,32)=512 threads, 32 rows/block, 3125 blocks exactly.
// ---------------------------------------------------------------------------
template <int L>
__global__ void __launch_bounds__(512) k_gemm(const float* __restrict__ Xin,
                                              const float* __restrict__ W) {
    __shared__ float Ws[64 * 64];
    __shared__ float Xs[32][65];

    const float* __restrict__ X = (L == 0) ? Xin : (const float*)g_z;

    const int tx = threadIdx.x, ty = threadIdx.y;
    const int tid = ty * 16 + tx;
    const int rowbase = blockIdx.x * 32;

    #pragma unroll
    for (int i = tid; i < 64 * 64; i += 512) Ws[i] = W[i];
    #pragma unroll
    for (int i = tid; i < 32 * 64; i += 512)
        Xs[i >> 6][i & 63] = X[(rowbase + (i >> 6)) * 64 + (i & 63)];
    __syncthreads();

    float a0 = 0.f, a1 = 0.f, a2 = 0.f, a3 = 0.f;
    #pragma unroll
    for (int k = 0; k < 64; k++) {
        float xv = Xs[ty][k];
        float4 w = *(const float4*)&Ws[k * 64 + tx * 4];
        a0 += xv * w.x; a1 += xv * w.y; a2 += xv * w.z; a3 += xv * w.w;
    }

    const int row = rowbase + ty;
    const float di = g_dinv[row];
    float4 o = make_float4(a0 * di, a1 * di, a2 * di, a3 * di);
    *(float4*)&g_hs[row * 64 + tx * 4] = o;
}

// ---------------------------------------------------------------------------
// z[node] = relu( dinv[node] * (hs[node] + sum_{s in N(node)} hs[s]) + b )
// One warp per node; each lane owns float2 at lane*2. Edge loop unrolled x4.
// ---------------------------------------------------------------------------
__global__ void __launch_bounds__(256) k_aggregate(const float* __restrict__ b) {
    const int t = blockIdx.x * blockDim.x + threadIdx.x;
    const int node = t >> 5;
    if (node >= N_NODES) return;
    const int lane = t & 31;
    const int c = lane * 2;

    float2 acc = *(const float2*)(g_hs + node * 64 + c);  // self loop

    int e   = g_start[node];
    const int end = e + g_indeg[node];

    for (; e + 4 <= end; e += 4) {
        int s0 = __ldg(&g_csr[e]);
        int s1 = __ldg(&g_csr[e + 1]);
        int s2 = __ldg(&g_csr[e + 2]);
        int s3 = __ldg(&g_csr[e + 3]);
        float2 v0 = __ldg((const float2*)(g_hs + s0 * 64 + c));
        float2 v1 = __ldg((const float2*)(g_hs + s1 * 64 + c));
        float2 v2 = __ldg((const float2*)(g_hs + s2 * 64 + c));
        float2 v3 = __ldg((const float2*)(g_hs + s3 * 64 + c));
        acc.x += v0.x + v1.x + v2.x + v3.x;
        acc.y += v0.y + v1.y + v2.y + v3.y;
    }
    for (; e < end; e++) {
        int s = __ldg(&g_csr[e]);
        float2 v = __ldg((const float2*)(g_hs + s * 64 + c));
        acc.x += v.x; acc.y += v.y;
    }

    const float di = g_dinv[node];
    float2 bb = *(const float2*)(b + c);
    float2 z;
    z.x = fmaxf(acc.x * di + bb.x, 0.0f);
    z.y = fmaxf(acc.y * di + bb.y, 0.0f);
    *(float2*)(g_z + node * 64 + c) = z;
}

// ---------------------------------------------------------------------------
// out[node] = z[node] . Wo + bo      (one warp per node)
// ---------------------------------------------------------------------------
__global__ void __launch_bounds__(256) k_readout(const float* __restrict__ Wo,
                                                 const float* __restrict__ bo,
                                                 float* __restrict__ out) {
    const int t = blockIdx.x * blockDim.x + threadIdx.x;
    const int node = t >> 5;
    if (node >= N_NODES) return;
    const int lane = t & 31;

    float2 z = *(const float2*)(g_z + node * 64 + lane * 2);
    float2 w = *(const float2*)(Wo + lane * 2);
    float sum = z.x * w.x + z.y * w.y;

    #pragma unroll
    for (int off = 16; off; off >>= 1)
        sum += __shfl_down_sync(0xffffffff, sum, off);

    if (lane == 0) out[node] = sum + bo[0];
}

// ---------------------------------------------------------------------------
extern "C" void kernel_launch(void* const* d_in, const int* in_sizes, int n_in,
                              void* d_out, int out_size) {
    const float* h  = (const float*)d_in[0];
    const void*  ei = d_in[1];               // [2,E]; dtype probed on device
    const float* W1 = (const float*)d_in[2];
    const float* b1 = (const float*)d_in[3];
    const float* W2 = (const float*)d_in[4];
    const float* b2 = (const float*)d_in[5];
    const float* Wo = (const float*)d_in[6];
    const float* bo = (const float*)d_in[7];
    float* out = (float*)d_out;

    k_detect<<<1, 64>>>((const long long*)ei);
    k_zero_indeg<<<(N_NODES + 255) / 256, 256>>>();
    k_count<<<(N_EDGES + 255) / 256, 256>>>(ei);
    k_scan1<<<N_SCANB, SCAN_B>>>();
    k_scan2<<<1, 256>>>();
    k_scan3<<<(N_NODES + 255) / 256, 256>>>();
    k_fill<<<(N_EDGES + 255) / 256, 256>>>(ei);

    dim3 gb(16, 32);
    k_gemm<0><<<N_NODES / 32, gb>>>(h, W1);
    k_aggregate<<<(N_NODES * 32 + 255) / 256, 256>>>(b1);
    k_gemm<1><<<N_NODES / 32, gb>>>(nullptr, W2);
    k_aggregate<<<(N_NODES * 32 + 255) / 256, 256>>>(b2);
    k_readout<<<(N_NODES * 32 + 255) / 256, 256>>>(Wo, bo, out);
}

// round 5
// speedup vs baseline: 1.6167x; 1.6167x over previous
#include <cuda_runtime.h>

#define N_NODES 100000
#define N_EDGES 1600000
#define F 64
#define SCAN_B 512
#define N_SCANB ((N_NODES + SCAN_B - 1) / SCAN_B)   // 196

// ---- scratch (static __device__, no allocation) ----
__device__ int   g_is64;                  // 1 if edge_index is int64, 0 if int32
__device__ int   g_indeg[N_NODES];
__device__ int   g_start[N_NODES];
__device__ int   g_cur[N_NODES];
__device__ int   g_bsum[256];
__device__ int   g_boff[256];
__device__ float g_dinv[N_NODES];
__device__ int   g_csr[N_EDGES];          // src node per CSR slot (grouped by dst)
__device__ float g_hs[N_NODES * F];       // (x @ W) * dinv[row]
__device__ float g_z[N_NODES * F];        // relu(dinv*sum + b)  (layer-1 activations)

// ---------------------------------------------------------------------------
// Fused: zero indeg over the whole grid; block 0 additionally probes the
// edge-index dtype (all-valid int64 interpretation => int64, else int32).
// ---------------------------------------------------------------------------
__global__ void k_init(const long long* __restrict__ p64) {
    int i = blockIdx.x * blockDim.x + threadIdx.x;
    if (i < N_NODES) g_indeg[i] = 0;
    if (blockIdx.x == 0) {
        __shared__ int ok;
        if (threadIdx.x == 0) ok = 1;
        __syncthreads();
        if (threadIdx.x < 64) {
            long long v = p64[threadIdx.x];
            if (v < 0 || v >= N_NODES) ok = 0;
        }
        __syncthreads();
        if (threadIdx.x == 0) g_is64 = ok;
    }
}

__global__ void k_count(const void* __restrict__ ei) {
    int e = blockIdx.x * blockDim.x + threadIdx.x;
    if (e >= N_EDGES) return;
    int d = g_is64 ? (int)((const long long*)ei)[N_EDGES + e]
                   : ((const int*)ei)[N_EDGES + e];
    if ((unsigned)d < N_NODES) atomicAdd(&g_indeg[d], 1);
}

// exclusive scan of indeg, 3-phase
__global__ void __launch_bounds__(SCAN_B) k_scan1() {
    __shared__ int sh[SCAN_B];
    int i = blockIdx.x * SCAN_B + threadIdx.x;
    int v = (i < N_NODES) ? g_indeg[i] : 0;
    sh[threadIdx.x] = v;
    __syncthreads();
    for (int off = 1; off < SCAN_B; off <<= 1) {
        int t = (threadIdx.x >= off) ? sh[threadIdx.x - off] : 0;
        __syncthreads();
        sh[threadIdx.x] += t;
        __syncthreads();
    }
    if (i < N_NODES) g_start[i] = sh[threadIdx.x] - v;  // exclusive within block
    if (threadIdx.x == SCAN_B - 1) g_bsum[blockIdx.x] = sh[SCAN_B - 1];
}

__global__ void __launch_bounds__(256) k_scan2() {
    __shared__ int sh[256];
    int v = (threadIdx.x < N_SCANB) ? g_bsum[threadIdx.x] : 0;
    sh[threadIdx.x] = v;
    __syncthreads();
    for (int off = 1; off < 256; off <<= 1) {
        int t = (threadIdx.x >= off) ? sh[threadIdx.x - off] : 0;
        __syncthreads();
        sh[threadIdx.x] += t;
        __syncthreads();
    }
    g_boff[threadIdx.x] = sh[threadIdx.x] - v;  // exclusive
}

__global__ void k_scan3() {
    int i = blockIdx.x * blockDim.x + threadIdx.x;
    if (i < N_NODES) {
        int st = g_start[i] + g_boff[i / SCAN_B];
        g_start[i] = st;
        g_cur[i]   = st;
        g_dinv[i]  = rsqrtf((float)(g_indeg[i] + 1));  // +1 self loop
    }
}

__global__ void k_fill(const void* __restrict__ ei) {
    int e = blockIdx.x * blockDim.x + threadIdx.x;
    if (e >= N_EDGES) return;
    int s, d;
    if (g_is64) {
        s = (int)((const long long*)ei)[e];
        d = (int)((const long long*)ei)[N_EDGES + e];
    } else {
        s = ((const int*)ei)[e];
        d = ((const int*)ei)[N_EDGES + e];
    }
    if ((unsigned)s < N_NODES && (unsigned)d < N_NODES) {
        int slot = atomicAdd(&g_cur[d], 1);
        if ((unsigned)slot < N_EDGES) g_csr[slot] = s;
    }
}

// ---------------------------------------------------------------------------
// hs = (X @ W) * dinv[row].   Register-blocked 4x4.
// Block: 256 threads (tx 0..15 = colgroup, ty 0..15 = rowgroup), tile 64x64.
// X staged TRANSPOSED in smem so both operands stream as LDS.128:
//   per k: 1 float4 of X rows + 1 float4 of W cols -> 16 FFMA  (2B LDS / FFMA)
// Blocks: ceil(100000/64) = 1563 (last block row-guarded).
//   L == 0: X = harness input pointer (raw h)
//   L == 1: X = g_z (device-side symbol reference only)
// ---------------------------------------------------------------------------
#define XT_PITCH 68   // 64 + 4 pad: keeps rows 16B-aligned, kills bank conflicts
template <int L>
__global__ void __launch_bounds__(256) k_gemm(const float* __restrict__ Xin,
                                              const float* __restrict__ W) {
    __shared__ float Ws[64 * 64];
    __shared__ float XsT[64 * XT_PITCH];

    const float* __restrict__ X = (L == 0) ? Xin : (const float*)g_z;

    const int tx = threadIdx.x & 15;
    const int ty = threadIdx.x >> 4;
    const int tid = threadIdx.x;
    const int rowbase = blockIdx.x * 64;

    #pragma unroll
    for (int i = tid; i < 64 * 64; i += 256) Ws[i] = W[i];
    #pragma unroll
    for (int i = tid; i < 64 * 64; i += 256) {
        int r = i >> 6, c = i & 63;
        int row = rowbase + r;
        float v = (row < N_NODES) ? X[row * 64 + c] : 0.0f;
        XsT[c * XT_PITCH + r] = v;
    }
    __syncthreads();

    float acc[4][4];
    #pragma unroll
    for (int i = 0; i < 4; i++)
        #pragma unroll
        for (int j = 0; j < 4; j++) acc[i][j] = 0.0f;

    #pragma unroll
    for (int k = 0; k < 64; k++) {
        float4 xv = *(const float4*)&XsT[k * XT_PITCH + ty * 4];
        float4 wv = *(const float4*)&Ws[k * 64 + tx * 4];
        acc[0][0] += xv.x * wv.x; acc[0][1] += xv.x * wv.y; acc[0][2] += xv.x * wv.z; acc[0][3] += xv.x * wv.w;
        acc[1][0] += xv.y * wv.x; acc[1][1] += xv.y * wv.y; acc[1][2] += xv.y * wv.z; acc[1][3] += xv.y * wv.w;
        acc[2][0] += xv.z * wv.x; acc[2][1] += xv.z * wv.y; acc[2][2] += xv.z * wv.z; acc[2][3] += xv.z * wv.w;
        acc[3][0] += xv.w * wv.x; acc[3][1] += xv.w * wv.y; acc[3][2] += xv.w * wv.z; acc[3][3] += xv.w * wv.w;
    }

    #pragma unroll
    for (int i = 0; i < 4; i++) {
        int row = rowbase + ty * 4 + i;
        if (row < N_NODES) {
            float di = g_dinv[row];
            float4 o = make_float4(acc[i][0] * di, acc[i][1] * di,
                                   acc[i][2] * di, acc[i][3] * di);
            *(float4*)&g_hs[row * 64 + tx * 4] = o;
        }
    }
}

// ---------------------------------------------------------------------------
// z[node] = relu( dinv[node] * (hs[node] + sum_{s in N(node)} hs[s]) + b )
// One warp per node; lane owns float2 at lane*2. Edge loop unrolled x8.
// FUSE_OUT == 0: write z to g_z (feeds next gemm)
// FUSE_OUT == 1: dot z with Wo, warp-reduce, write out[node] (readout fused)
// ---------------------------------------------------------------------------
template <int FUSE_OUT>
__global__ void __launch_bounds__(256) k_aggregate(const float* __restrict__ b,
                                                   const float* __restrict__ Wo,
                                                   const float* __restrict__ bo,
                                                   float* __restrict__ out) {
    const int t = blockIdx.x * blockDim.x + threadIdx.x;
    const int node = t >> 5;
    if (node >= N_NODES) return;
    const int lane = t & 31;
    const int c = lane * 2;

    float2 acc = *(const float2*)(g_hs + node * 64 + c);  // self loop

    int e   = g_start[node];
    const int end = e + g_indeg[node];

    for (; e + 8 <= end; e += 8) {
        int s0 = __ldg(&g_csr[e]);
        int s1 = __ldg(&g_csr[e + 1]);
        int s2 = __ldg(&g_csr[e + 2]);
        int s3 = __ldg(&g_csr[e + 3]);
        int s4 = __ldg(&g_csr[e + 4]);
        int s5 = __ldg(&g_csr[e + 5]);
        int s6 = __ldg(&g_csr[e + 6]);
        int s7 = __ldg(&g_csr[e + 7]);
        float2 v0 = __ldg((const float2*)(g_hs + s0 * 64 + c));
        float2 v1 = __ldg((const float2*)(g_hs + s1 * 64 + c));
        float2 v2 = __ldg((const float2*)(g_hs + s2 * 64 + c));
        float2 v3 = __ldg((const float2*)(g_hs + s3 * 64 + c));
        float2 v4 = __ldg((const float2*)(g_hs + s4 * 64 + c));
        float2 v5 = __ldg((const float2*)(g_hs + s5 * 64 + c));
        float2 v6 = __ldg((const float2*)(g_hs + s6 * 64 + c));
        float2 v7 = __ldg((const float2*)(g_hs + s7 * 64 + c));
        acc.x += (v0.x + v1.x) + (v2.x + v3.x) + ((v4.x + v5.x) + (v6.x + v7.x));
        acc.y += (v0.y + v1.y) + (v2.y + v3.y) + ((v4.y + v5.y) + (v6.y + v7.y));
    }
    for (; e < end; e++) {
        int s = __ldg(&g_csr[e]);
        float2 v = __ldg((const float2*)(g_hs + s * 64 + c));
        acc.x += v.x; acc.y += v.y;
    }

    const float di = g_dinv[node];
    float2 bb = *(const float2*)(b + c);
    float zx = fmaxf(acc.x * di + bb.x, 0.0f);
    float zy = fmaxf(acc.y * di + bb.y, 0.0f);

    if constexpr (FUSE_OUT == 0) {
        *(float2*)(g_z + node * 64 + c) = make_float2(zx, zy);
    } else {
        float2 w = *(const float2*)(Wo + c);
        float sum = zx * w.x + zy * w.y;
        #pragma unroll
        for (int off = 16; off; off >>= 1)
            sum += __shfl_down_sync(0xffffffff, sum, off);
        if (lane == 0) out[node] = sum + bo[0];
    }
}

// ---------------------------------------------------------------------------
extern "C" void kernel_launch(void* const* d_in, const int* in_sizes, int n_in,
                              void* d_out, int out_size) {
    const float* h  = (const float*)d_in[0];
    const void*  ei = d_in[1];               // [2,E]; dtype probed on device
    const float* W1 = (const float*)d_in[2];
    const float* b1 = (const float*)d_in[3];
    const float* W2 = (const float*)d_in[4];
    const float* b2 = (const float*)d_in[5];
    const float* Wo = (const float*)d_in[6];
    const float* bo = (const float*)d_in[7];
    float* out = (float*)d_out;

    k_init<<<(N_NODES + 255) / 256, 256>>>((const long long*)ei);
    k_count<<<(N_EDGES + 255) / 256, 256>>>(ei);
    k_scan1<<<N_SCANB, SCAN_B>>>();
    k_scan2<<<1, 256>>>();
    k_scan3<<<(N_NODES + 255) / 256, 256>>>();
    k_fill<<<(N_EDGES + 255) / 256, 256>>>(ei);

    k_gemm<0><<<(N_NODES + 63) / 64, 256>>>(h, W1);
    k_aggregate<0><<<(N_NODES * 32 + 255) / 256, 256>>>(b1, nullptr, nullptr, nullptr);
    k_gemm<1><<<(N_NODES + 63) / 64, 256>>>(nullptr, W2);
    k_aggregate<1><<<(N_NODES * 32 + 255) / 256, 256>>>(b2, Wo, bo, out);
}

// round 6
// speedup vs baseline: 1.6276x; 1.0068x over previous
#include <cuda_runtime.h>
#include <cuda_fp16.h>

#define N_NODES 100000
#define N_EDGES 1600000
#define F 64
#define SCAN_B 512
#define N_SCANB ((N_NODES + SCAN_B - 1) / SCAN_B)   // 196

// ---- scratch (static __device__, no allocation) ----
__device__ int     g_is64;                 // 1 if edge_index is int64, 0 if int32
__device__ int     g_indeg[N_NODES];
__device__ int     g_start[N_NODES];
__device__ int     g_cur[N_NODES];
__device__ int     g_bsum[256];
__device__ int     g_boff[256];
__device__ float   g_dinv[N_NODES];
__device__ int     g_csr[N_EDGES];         // src node per CSR slot (grouped by dst)
__device__ __half2 g_hsh[N_NODES * 32];    // (x @ W) * dinv[row], fp16 pairs (32 half2/row)
__device__ float   g_z[N_NODES * F];       // relu(dinv*sum + b)  (layer-1 activations, fp32)

// ---------------------------------------------------------------------------
// Fused: zero indeg; block 0 probes edge-index dtype.
// ---------------------------------------------------------------------------
__global__ void k_init(const long long* __restrict__ p64) {
    int i = blockIdx.x * blockDim.x + threadIdx.x;
    if (i < N_NODES) g_indeg[i] = 0;
    if (blockIdx.x == 0) {
        __shared__ int ok;
        if (threadIdx.x == 0) ok = 1;
        __syncthreads();
        if (threadIdx.x < 64) {
            long long v = p64[threadIdx.x];
            if (v < 0 || v >= N_NODES) ok = 0;
        }
        __syncthreads();
        if (threadIdx.x == 0) g_is64 = ok;
    }
}

__global__ void k_count(const void* __restrict__ ei) {
    int e = blockIdx.x * blockDim.x + threadIdx.x;
    if (e >= N_EDGES) return;
    int d = g_is64 ? (int)((const long long*)ei)[N_EDGES + e]
                   : ((const int*)ei)[N_EDGES + e];
    if ((unsigned)d < N_NODES) atomicAdd(&g_indeg[d], 1);
}

// exclusive scan of indeg, 3-phase
__global__ void __launch_bounds__(SCAN_B) k_scan1() {
    __shared__ int sh[SCAN_B];
    int i = blockIdx.x * SCAN_B + threadIdx.x;
    int v = (i < N_NODES) ? g_indeg[i] : 0;
    sh[threadIdx.x] = v;
    __syncthreads();
    for (int off = 1; off < SCAN_B; off <<= 1) {
        int t = (threadIdx.x >= off) ? sh[threadIdx.x - off] : 0;
        __syncthreads();
        sh[threadIdx.x] += t;
        __syncthreads();
    }
    if (i < N_NODES) g_start[i] = sh[threadIdx.x] - v;
    if (threadIdx.x == SCAN_B - 1) g_bsum[blockIdx.x] = sh[SCAN_B - 1];
}

__global__ void __launch_bounds__(256) k_scan2() {
    __shared__ int sh[256];
    int v = (threadIdx.x < N_SCANB) ? g_bsum[threadIdx.x] : 0;
    sh[threadIdx.x] = v;
    __syncthreads();
    for (int off = 1; off < 256; off <<= 1) {
        int t = (threadIdx.x >= off) ? sh[threadIdx.x - off] : 0;
        __syncthreads();
        sh[threadIdx.x] += t;
        __syncthreads();
    }
    g_boff[threadIdx.x] = sh[threadIdx.x] - v;
}

__global__ void k_scan3() {
    int i = blockIdx.x * blockDim.x + threadIdx.x;
    if (i < N_NODES) {
        int st = g_start[i] + g_boff[i / SCAN_B];
        g_start[i] = st;
        g_cur[i]   = st;
        g_dinv[i]  = rsqrtf((float)(g_indeg[i] + 1));  // +1 self loop
    }
}

__global__ void k_fill(const void* __restrict__ ei) {
    int e = blockIdx.x * blockDim.x + threadIdx.x;
    if (e >= N_EDGES) return;
    int s, d;
    if (g_is64) {
        s = (int)((const long long*)ei)[e];
        d = (int)((const long long*)ei)[N_EDGES + e];
    } else {
        s = ((const int*)ei)[e];
        d = ((const int*)ei)[N_EDGES + e];
    }
    if ((unsigned)s < N_NODES && (unsigned)d < N_NODES) {
        int slot = atomicAdd(&g_cur[d], 1);
        if ((unsigned)slot < N_EDGES) g_csr[slot] = s;
    }
}

// ---------------------------------------------------------------------------
// hs = (X @ W) * dinv[row], stored as fp16 pairs.  Register-blocked 4x4,
// 64x64 tile, 256 threads; X staged transposed so both operands are LDS.128.
//   L == 0: X = harness input pointer (raw h)
//   L == 1: X = g_z (device-side symbol reference only)
// ---------------------------------------------------------------------------
#define XT_PITCH 68
template <int L>
__global__ void __launch_bounds__(256) k_gemm(const float* __restrict__ Xin,
                                              const float* __restrict__ W) {
    __shared__ float Ws[64 * 64];
    __shared__ float XsT[64 * XT_PITCH];

    const float* __restrict__ X = (L == 0) ? Xin : (const float*)g_z;

    const int tx = threadIdx.x & 15;
    const int ty = threadIdx.x >> 4;
    const int tid = threadIdx.x;
    const int rowbase = blockIdx.x * 64;

    #pragma unroll
    for (int i = tid; i < 64 * 64; i += 256) Ws[i] = W[i];
    #pragma unroll
    for (int i = tid; i < 64 * 64; i += 256) {
        int r = i >> 6, c = i & 63;
        int row = rowbase + r;
        float v = (row < N_NODES) ? X[row * 64 + c] : 0.0f;
        XsT[c * XT_PITCH + r] = v;
    }
    __syncthreads();

    float acc[4][4];
    #pragma unroll
    for (int i = 0; i < 4; i++)
        #pragma unroll
        for (int j = 0; j < 4; j++) acc[i][j] = 0.0f;

    #pragma unroll
    for (int k = 0; k < 64; k++) {
        float4 xv = *(const float4*)&XsT[k * XT_PITCH + ty * 4];
        float4 wv = *(const float4*)&Ws[k * 64 + tx * 4];
        acc[0][0] += xv.x * wv.x; acc[0][1] += xv.x * wv.y; acc[0][2] += xv.x * wv.z; acc[0][3] += xv.x * wv.w;
        acc[1][0] += xv.y * wv.x; acc[1][1] += xv.y * wv.y; acc[1][2] += xv.y * wv.z; acc[1][3] += xv.y * wv.w;
        acc[2][0] += xv.z * wv.x; acc[2][1] += xv.z * wv.y; acc[2][2] += xv.z * wv.z; acc[2][3] += xv.z * wv.w;
        acc[3][0] += xv.w * wv.x; acc[3][1] += xv.w * wv.y; acc[3][2] += xv.w * wv.z; acc[3][3] += xv.w * wv.w;
    }

    #pragma unroll
    for (int i = 0; i < 4; i++) {
        int row = rowbase + ty * 4 + i;
        if (row < N_NODES) {
            float di = g_dinv[row];
            __half2 h0 = __floats2half2_rn(acc[i][0] * di, acc[i][1] * di);
            __half2 h1 = __floats2half2_rn(acc[i][2] * di, acc[i][3] * di);
            // cols tx*4..tx*4+3 -> half2 slots row*32 + tx*2, +1 (8B store)
            uint2 pk;
            pk.x = *(const unsigned int*)&h0;
            pk.y = *(const unsigned int*)&h1;
            *(uint2*)&g_hsh[row * 32 + tx * 2] = pk;
        }
    }
}

// ---------------------------------------------------------------------------
// z[node] = relu( dinv[node] * (hs[node] + sum_{s in N(node)} hs[s]) + b )
// One warp per node; lane owns half2 slot `lane` (cols 2l,2l+1), fp32 accum.
// FUSE_OUT == 0: write z (fp32) to g_z.   FUSE_OUT == 1: fused readout.
// ---------------------------------------------------------------------------
template <int FUSE_OUT>
__global__ void __launch_bounds__(256) k_aggregate(const float* __restrict__ b,
                                                   const float* __restrict__ Wo,
                                                   const float* __restrict__ bo,
                                                   float* __restrict__ out) {
    const int t = blockIdx.x * blockDim.x + threadIdx.x;
    const int node = t >> 5;
    if (node >= N_NODES) return;
    const int lane = t & 31;

    float2 acc = __half22float2(g_hsh[node * 32 + lane]);  // self loop

    int e   = g_start[node];
    const int end = e + g_indeg[node];

    for (; e + 8 <= end; e += 8) {
        int s0 = __ldg(&g_csr[e]);
        int s1 = __ldg(&g_csr[e + 1]);
        int s2 = __ldg(&g_csr[e + 2]);
        int s3 = __ldg(&g_csr[e + 3]);
        int s4 = __ldg(&g_csr[e + 4]);
        int s5 = __ldg(&g_csr[e + 5]);
        int s6 = __ldg(&g_csr[e + 6]);
        int s7 = __ldg(&g_csr[e + 7]);
        float2 v0 = __half22float2(__ldg(&g_hsh[s0 * 32 + lane]));
        float2 v1 = __half22float2(__ldg(&g_hsh[s1 * 32 + lane]));
        float2 v2 = __half22float2(__ldg(&g_hsh[s2 * 32 + lane]));
        float2 v3 = __half22float2(__ldg(&g_hsh[s3 * 32 + lane]));
        float2 v4 = __half22float2(__ldg(&g_hsh[s4 * 32 + lane]));
        float2 v5 = __half22float2(__ldg(&g_hsh[s5 * 32 + lane]));
        float2 v6 = __half22float2(__ldg(&g_hsh[s6 * 32 + lane]));
        float2 v7 = __half22float2(__ldg(&g_hsh[s7 * 32 + lane]));
        acc.x += ((v0.x + v1.x) + (v2.x + v3.x)) + ((v4.x + v5.x) + (v6.x + v7.x));
        acc.y += ((v0.y + v1.y) + (v2.y + v3.y)) + ((v4.y + v5.y) + (v6.y + v7.y));
    }
    for (; e < end; e++) {
        int s = __ldg(&g_csr[e]);
        float2 v = __half22float2(__ldg(&g_hsh[s * 32 + lane]));
        acc.x += v.x; acc.y += v.y;
    }

    const float di = g_dinv[node];
    const int c = lane * 2;
    float2 bb = *(const float2*)(b + c);
    float zx = fmaxf(acc.x * di + bb.x, 0.0f);
    float zy = fmaxf(acc.y * di + bb.y, 0.0f);

    if constexpr (FUSE_OUT == 0) {
        *(float2*)(g_z + node * 64 + c) = make_float2(zx, zy);
    } else {
        float2 w = *(const float2*)(Wo + c);
        float sum = zx * w.x + zy * w.y;
        #pragma unroll
        for (int off = 16; off; off >>= 1)
            sum += __shfl_down_sync(0xffffffff, sum, off);
        if (lane == 0) out[node] = sum + bo[0];
    }
}

// ---------------------------------------------------------------------------
extern "C" void kernel_launch(void* const* d_in, const int* in_sizes, int n_in,
                              void* d_out, int out_size) {
    const float* h  = (const float*)d_in[0];
    const void*  ei = d_in[1];               // [2,E]; dtype probed on device
    const float* W1 = (const float*)d_in[2];
    const float* b1 = (const float*)d_in[3];
    const float* W2 = (const float*)d_in[4];
    const float* b2 = (const float*)d_in[5];
    const float* Wo = (const float*)d_in[6];
    const float* bo = (const float*)d_in[7];
    float* out = (float*)d_out;

    k_init<<<(N_NODES + 255) / 256, 256>>>((const long long*)ei);
    k_count<<<(N_EDGES + 255) / 256, 256>>>(ei);
    k_scan1<<<N_SCANB, SCAN_B>>>();
    k_scan2<<<1, 256>>>();
    k_scan3<<<(N_NODES + 255) / 256, 256>>>();
    k_fill<<<(N_EDGES + 255) / 256, 256>>>(ei);

    k_gemm<0><<<(N_NODES + 63) / 64, 256>>>(h, W1);
    k_aggregate<0><<<(N_NODES * 32 + 255) / 256, 256>>>(b1, nullptr, nullptr, nullptr);
    k_gemm<1><<<(N_NODES + 63) / 64, 256>>>(nullptr, W2);
    k_aggregate<1><<<(N_NODES * 32 + 255) / 256, 256>>>(b2, Wo, bo, out);
}

// round 7
// speedup vs baseline: 1.7041x; 1.0470x over previous
#include <cuda_runtime.h>
#include <cuda_fp16.h>

#define N_NODES 100000
#define N_EDGES 1600000
#define F 64
#define SCAN_B 512
#define N_SCANB ((N_NODES + SCAN_B - 1) / SCAN_B)   // 196

// ---- scratch (static __device__, no allocation) ----
__device__ int     g_is64;                 // 1 if edge_index is int64, 0 if int32
__device__ int     g_done;                 // last-block-done counter for the scan
__device__ int     g_indeg[N_NODES];
__device__ int     g_start[N_NODES];       // local-exclusive (within scan block)
__device__ int     g_cur[N_NODES];         // local bump counters
__device__ int     g_bsum[SCAN_B];
__device__ int     g_boff[SCAN_B];         // exclusive block offsets
__device__ float   g_dinv[N_NODES];
__device__ int     g_csr[N_EDGES];         // src node per CSR slot (grouped by dst)
__device__ __half2 g_hsh[N_NODES * 32];    // (x @ W) * dinv[row], fp16 pairs
__device__ float   g_z[N_NODES * F];       // layer-1 activations (fp32)

// ---------------------------------------------------------------------------
// Fused: zero indeg + done counter; block 0 probes edge-index dtype.
// ---------------------------------------------------------------------------
__global__ void k_init(const long long* __restrict__ p64) {
    int i = blockIdx.x * blockDim.x + threadIdx.x;
    if (i < N_NODES) g_indeg[i] = 0;
    if (i == 0) g_done = 0;
    if (blockIdx.x == 0) {
        __shared__ int ok;
        if (threadIdx.x == 0) ok = 1;
        __syncthreads();
        if (threadIdx.x < 64) {
            long long v = p64[threadIdx.x];
            if (v < 0 || v >= N_NODES) ok = 0;
        }
        __syncthreads();
        if (threadIdx.x == 0) g_is64 = ok;
    }
}

__global__ void k_count(const void* __restrict__ ei) {
    int e = blockIdx.x * blockDim.x + threadIdx.x;
    if (e >= N_EDGES) return;
    int d = g_is64 ? (int)((const long long*)ei)[N_EDGES + e]
                   : ((const int*)ei)[N_EDGES + e];
    if ((unsigned)d < N_NODES) atomicAdd(&g_indeg[d], 1);
}

// ---------------------------------------------------------------------------
// Single-kernel scan: per-block exclusive scan of indeg (+dinv, +cur init);
// the LAST block to finish scans the 196 block sums into g_boff.
// Consumers add g_boff[node >> 9].
// ---------------------------------------------------------------------------
__global__ void __launch_bounds__(SCAN_B) k_scan() {
    __shared__ int sh[SCAN_B];
    __shared__ int amLast;
    int i = blockIdx.x * SCAN_B + threadIdx.x;
    int v = (i < N_NODES) ? g_indeg[i] : 0;
    sh[threadIdx.x] = v;
    __syncthreads();
    for (int off = 1; off < SCAN_B; off <<= 1) {
        int t = (threadIdx.x >= off) ? sh[threadIdx.x - off] : 0;
        __syncthreads();
        sh[threadIdx.x] += t;
        __syncthreads();
    }
    if (i < N_NODES) {
        int ex = sh[threadIdx.x] - v;
        g_start[i] = ex;
        g_cur[i]   = ex;
        g_dinv[i]  = rsqrtf((float)(v + 1));   // +1 self loop
    }
    if (threadIdx.x == SCAN_B - 1) g_bsum[blockIdx.x] = sh[SCAN_B - 1];
    __threadfence();
    __syncthreads();
    if (threadIdx.x == 0)
        amLast = (atomicAdd(&g_done, 1) == (int)gridDim.x - 1);
    __syncthreads();
    if (amLast) {
        __threadfence();  // acquire: see all blocks' g_bsum
        int bv = (threadIdx.x < N_SCANB) ? g_bsum[threadIdx.x] : 0;
        sh[threadIdx.x] = bv;
        __syncthreads();
        for (int off = 1; off < SCAN_B; off <<= 1) {
            int t = (threadIdx.x >= off) ? sh[threadIdx.x - off] : 0;
            __syncthreads();
            sh[threadIdx.x] += t;
            __syncthreads();
        }
        if (threadIdx.x < N_SCANB) g_boff[threadIdx.x] = sh[threadIdx.x] - bv;
    }
}

__global__ void k_fill(const void* __restrict__ ei) {
    int e = blockIdx.x * blockDim.x + threadIdx.x;
    if (e >= N_EDGES) return;
    int s, d;
    if (g_is64) {
        s = (int)((const long long*)ei)[e];
        d = (int)((const long long*)ei)[N_EDGES + e];
    } else {
        s = ((const int*)ei)[e];
        d = ((const int*)ei)[N_EDGES + e];
    }
    if ((unsigned)s < N_NODES && (unsigned)d < N_NODES) {
        int slot = atomicAdd(&g_cur[d], 1) + g_boff[d >> 9];
        if ((unsigned)slot < N_EDGES) g_csr[slot] = s;
    }
}

// ---------------------------------------------------------------------------
// hs = (X @ W) * dinv[row], stored fp16.  Register-blocked 4x4, 64x64 tile.
//   L == 0: X = harness input (raw h);  L == 1: X = g_z (device symbol)
// ---------------------------------------------------------------------------
#define XT_PITCH 68
template <int L>
__global__ void __launch_bounds__(256) k_gemm(const float* __restrict__ Xin,
                                              const float* __restrict__ W) {
    __shared__ float Ws[64 * 64];
    __shared__ float XsT[64 * XT_PITCH];

    const float* __restrict__ X = (L == 0) ? Xin : (const float*)g_z;

    const int tx = threadIdx.x & 15;
    const int ty = threadIdx.x >> 4;
    const int tid = threadIdx.x;
    const int rowbase = blockIdx.x * 64;

    #pragma unroll
    for (int i = tid; i < 64 * 64; i += 256) Ws[i] = W[i];
    #pragma unroll
    for (int i = tid; i < 64 * 64; i += 256) {
        int r = i >> 6, c = i & 63;
        int row = rowbase + r;
        float v = (row < N_NODES) ? X[row * 64 + c] : 0.0f;
        XsT[c * XT_PITCH + r] = v;
    }
    __syncthreads();

    float acc[4][4];
    #pragma unroll
    for (int i = 0; i < 4; i++)
        #pragma unroll
        for (int j = 0; j < 4; j++) acc[i][j] = 0.0f;

    #pragma unroll
    for (int k = 0; k < 64; k++) {
        float4 xv = *(const float4*)&XsT[k * XT_PITCH + ty * 4];
        float4 wv = *(const float4*)&Ws[k * 64 + tx * 4];
        acc[0][0] += xv.x * wv.x; acc[0][1] += xv.x * wv.y; acc[0][2] += xv.x * wv.z; acc[0][3] += xv.x * wv.w;
        acc[1][0] += xv.y * wv.x; acc[1][1] += xv.y * wv.y; acc[1][2] += xv.y * wv.z; acc[1][3] += xv.y * wv.w;
        acc[2][0] += xv.z * wv.x; acc[2][1] += xv.z * wv.y; acc[2][2] += xv.z * wv.z; acc[2][3] += xv.z * wv.w;
        acc[3][0] += xv.w * wv.x; acc[3][1] += xv.w * wv.y; acc[3][2] += xv.w * wv.z; acc[3][3] += xv.w * wv.w;
    }

    #pragma unroll
    for (int i = 0; i < 4; i++) {
        int row = rowbase + ty * 4 + i;
        if (row < N_NODES) {
            float di = g_dinv[row];
            __half2 h0 = __floats2half2_rn(acc[i][0] * di, acc[i][1] * di);
            __half2 h1 = __floats2half2_rn(acc[i][2] * di, acc[i][3] * di);
            uint2 pk;
            pk.x = *(const unsigned int*)&h0;
            pk.y = *(const unsigned int*)&h1;
            *(uint2*)&g_hsh[row * 32 + tx * 2] = pk;
        }
    }
}

// ---------------------------------------------------------------------------
// z[node] = relu( dinv[node] * (hs[node] + sum_{neigh} hs[s]) + b )
// One warp per node; lane owns half2 slot `lane`; fp32 accum; unroll x8.
// FUSE_OUT == 0: write z to g_z.   FUSE_OUT == 1: fused linear readout.
// ---------------------------------------------------------------------------
template <int FUSE_OUT>
__global__ void __launch_bounds__(256) k_aggregate(const float* __restrict__ b,
                                                   const float* __restrict__ Wo,
                                                   const float* __restrict__ bo,
                                                   float* __restrict__ out) {
    const int t = blockIdx.x * blockDim.x + threadIdx.x;
    const int node = t >> 5;
    if (node >= N_NODES) return;
    const int lane = t & 31;

    float2 acc = __half22float2(g_hsh[node * 32 + lane]);  // self loop

    int e   = g_start[node] + g_boff[node >> 9];
    const int end = e + g_indeg[node];

    for (; e + 8 <= end; e += 8) {
        int s0 = __ldg(&g_csr[e]);
        int s1 = __ldg(&g_csr[e + 1]);
        int s2 = __ldg(&g_csr[e + 2]);
        int s3 = __ldg(&g_csr[e + 3]);
        int s4 = __ldg(&g_csr[e + 4]);
        int s5 = __ldg(&g_csr[e + 5]);
        int s6 = __ldg(&g_csr[e + 6]);
        int s7 = __ldg(&g_csr[e + 7]);
        float2 v0 = __half22float2(__ldg(&g_hsh[s0 * 32 + lane]));
        float2 v1 = __half22float2(__ldg(&g_hsh[s1 * 32 + lane]));
        float2 v2 = __half22float2(__ldg(&g_hsh[s2 * 32 + lane]));
        float2 v3 = __half22float2(__ldg(&g_hsh[s3 * 32 + lane]));
        float2 v4 = __half22float2(__ldg(&g_hsh[s4 * 32 + lane]));
        float2 v5 = __half22float2(__ldg(&g_hsh[s5 * 32 + lane]));
        float2 v6 = __half22float2(__ldg(&g_hsh[s6 * 32 + lane]));
        float2 v7 = __half22float2(__ldg(&g_hsh[s7 * 32 + lane]));
        acc.x += ((v0.x + v1.x) + (v2.x + v3.x)) + ((v4.x + v5.x) + (v6.x + v7.x));
        acc.y += ((v0.y + v1.y) + (v2.y + v3.y)) + ((v4.y + v5.y) + (v6.y + v7.y));
    }
    for (; e < end; e++) {
        int s = __ldg(&g_csr[e]);
        float2 v = __half22float2(__ldg(&g_hsh[s * 32 + lane]));
        acc.x += v.x; acc.y += v.y;
    }

    const float di = g_dinv[node];
    const int c = lane * 2;
    float2 bb = *(const float2*)(b + c);
    float zx = fmaxf(acc.x * di + bb.x, 0.0f);
    float zy = fmaxf(acc.y * di + bb.y, 0.0f);

    if constexpr (FUSE_OUT == 0) {
        *(float2*)(g_z + node * 64 + c) = make_float2(zx, zy);
    } else {
        float2 w = *(const float2*)(Wo + c);
        float sum = zx * w.x + zy * w.y;
        #pragma unroll
        for (int off = 16; off; off >>= 1)
            sum += __shfl_down_sync(0xffffffff, sum, off);
        if (lane == 0) out[node] = sum + bo[0];
    }
}

// ---------------------------------------------------------------------------
extern "C" void kernel_launch(void* const* d_in, const int* in_sizes, int n_in,
                              void* d_out, int out_size) {
    const float* h  = (const float*)d_in[0];
    const void*  ei = d_in[1];               // [2,E]; dtype probed on device
    const float* W1 = (const float*)d_in[2];
    const float* b1 = (const float*)d_in[3];
    const float* W2 = (const float*)d_in[4];
    const float* b2 = (const float*)d_in[5];
    const float* Wo = (const float*)d_in[6];
    const float* bo = (const float*)d_in[7];
    float* out = (float*)d_out;

    // Fork gemm0 (independent of CSR build) onto a second stream.
    cudaStream_t s2;
    cudaStreamCreateWithFlags(&s2, cudaStreamNonBlocking);
    cudaEvent_t eFork, eJoin;
    cudaEventCreateWithFlags(&eFork, cudaEventDisableTiming);
    cudaEventCreateWithFlags(&eJoin, cudaEventDisableTiming);

    cudaEventRecord(eFork, 0);
    cudaStreamWaitEvent(s2, eFork, 0);

    // Branch A (stream s2): feature transform for layer 1 (needs dinv? NO —
    // wait: gemm epilogue multiplies by dinv, which the scan produces!)
    // -> gemm0 must wait for k_scan. Fork AFTER scan instead: overlap gemm0
    //    with k_fill (the biggest CSR stage).
    // Main stream: init, count, scan.
    k_init<<<(N_NODES + 255) / 256, 256>>>((const long long*)ei);
    k_count<<<(N_EDGES + 255) / 256, 256>>>(ei);
    k_scan<<<N_SCANB, SCAN_B>>>();

    cudaEventRecord(eFork, 0);
    cudaStreamWaitEvent(s2, eFork, 0);
    k_gemm<0><<<(N_NODES + 63) / 64, 256, 0, s2>>>(h, W1);   // overlaps k_fill
    cudaEventRecord(eJoin, s2);

    k_fill<<<(N_EDGES + 255) / 256, 256>>>(ei);

    cudaStreamWaitEvent(0, eJoin, 0);
    k_aggregate<0><<<(N_NODES * 32 + 255) / 256, 256>>>(b1, nullptr, nullptr, nullptr);
    k_gemm<1><<<(N_NODES + 63) / 64, 256>>>(nullptr, W2);
    k_aggregate<1><<<(N_NODES * 32 + 255) / 256, 256>>>(b2, Wo, bo, out);

    cudaEventDestroy(eFork);
    cudaEventDestroy(eJoin);
    cudaStreamDestroy(s2);
}